// round 1
// baseline (speedup 1.0000x reference)
#include <cuda_runtime.h>

// Problem constants (fixed shapes from reference)
#define TT 12
#define BB 8
#define EE 32
#define NN 192
#define NPAD 193                  // pad row to 193 words -> conflict-free both axes
#define NPAIRS (BB * EE)          // 256
#define TSTRIDE (BB * EE * NN)    // element stride between consecutive t slices
#define SMEM_BYTES (NN * NPAD * sizeof(float))   // 148224 B

// One CTA per (b,e) pair. H lives in (dynamic) shared memory, padded.
// Per step t:
//   row pass   : Hy[i]  = sum_j H[i][j] * y_t[j]          (thread i owns row i)
//   reduction  : sdot = s.y, yHy = y.Hy  -> c1, c2
//   update pass: thread j owns column j:
//       H[i][j] += p*s[i] + q*Hy[i],  p = c1*s[j] - c2*yH[j], q = -c2*s[j]
//     fused with yH_{t+1}[j] = sum_i y_{t+1}[i] * H_new[i][j]  (thread-local!)
// yH never needs SMEM; Hy does (broadcast in update pass).
__global__ void __launch_bounds__(NN, 1)
bfgs_kernel(const float* __restrict__ H0,
            const float* __restrict__ steps,
            const float* __restrict__ dgs,
            float* __restrict__ out)
{
    extern __shared__ float H[];                    // NN * NPAD floats
    __shared__ __align__(16) float sbuf[2][NN];
    __shared__ __align__(16) float ybuf[2][NN];
    __shared__ __align__(16) float Hys[NN];
    __shared__ float wp1[8], wp2[8];
    __shared__ float csh[2];

    const int tid  = threadIdx.x;
    const int pair = blockIdx.x;                    // b*EE + e
    const int lane = tid & 31;
    const int wid  = tid >> 5;

    const float* sb = steps + (size_t)pair * NN + tid;
    const float* yb = dgs   + (size_t)pair * NN + tid;

    // Load H0 into padded SMEM (coalesced per-row; H0 stays L2-resident)
    #pragma unroll 4
    for (int i = 0; i < NN; i++)
        H[i * NPAD + tid] = H0[i * NN + tid];

    float s_reg = sb[0];                            // s_0[tid]
    float y_reg = yb[0];                            // y_0[tid]
    sbuf[0][tid] = s_reg;
    ybuf[0][tid] = y_reg;
    __syncthreads();

    // Initial yH_0[tid] = sum_i y_0[i] * H0[i][tid]   (column pass, conflict-free)
    float yH_reg = 0.f;
    {
        const float4* y4 = (const float4*)ybuf[0];
        #pragma unroll 8
        for (int i4 = 0; i4 < NN / 4; i4++) {
            float4 yy = y4[i4];
            int i = i4 * 4;
            yH_reg += yy.x * H[(i    ) * NPAD + tid];
            yH_reg += yy.y * H[(i + 1) * NPAD + tid];
            yH_reg += yy.z * H[(i + 2) * NPAD + tid];
            yH_reg += yy.w * H[(i + 3) * NPAD + tid];
        }
    }

    for (int t = 0; t < TT; t++) {
        const int cur = t & 1, nxt = cur ^ 1;

        // Prefetch next step's s,y early to hide global latency
        float s_n = 0.f, y_n = 0.f;
        if (t + 1 < TT) {
            s_n = sb[(size_t)(t + 1) * TSTRIDE];
            y_n = yb[(size_t)(t + 1) * TSTRIDE];
        }

        // ---- Row pass: Hy[tid] = sum_j H[tid][j] * y_t[j] ----
        float hy = 0.f;
        {
            const float4* y4  = (const float4*)ybuf[cur];
            const float* hrow = H + tid * NPAD;     // lane-stride 193 -> bank=lane
            #pragma unroll 8
            for (int j4 = 0; j4 < NN / 4; j4++) {
                float4 yy = y4[j4];
                int j = j4 * 4;
                hy += hrow[j    ] * yy.x;
                hy += hrow[j + 1] * yy.y;
                hy += hrow[j + 2] * yy.z;
                hy += hrow[j + 3] * yy.w;
            }
        }
        Hys[tid] = hy;

        // ---- Reductions: sdot = s.y, yHy = y.Hy ----
        float v1 = s_reg * y_reg;
        float v2 = y_reg * hy;
        #pragma unroll
        for (int off = 16; off > 0; off >>= 1) {
            v1 += __shfl_down_sync(0xffffffffu, v1, off);
            v2 += __shfl_down_sync(0xffffffffu, v2, off);
        }
        if (lane == 0) { wp1[wid] = v1; wp2[wid] = v2; }

        // Stash next-step vectors (buffers are dead until after barrier C below)
        sbuf[nxt][tid] = s_n;
        ybuf[nxt][tid] = y_n;
        __syncthreads();                            // (A) Hys, wp*, next bufs visible

        if (tid == 0) {
            float sdot = 0.f, yHy = 0.f;
            #pragma unroll
            for (int w = 0; w < NN / 32; w++) { sdot += wp1[w]; yHy += wp2[w]; }
            float c1, c2;
            if (sdot != 0.f) { c2 = 1.f / sdot; c1 = (sdot + yHy) * c2 * c2; }
            else             { c1 = 0.f; c2 = 0.f; }   // masked update (reference)
            csh[0] = c1; csh[1] = c2;
        }
        __syncthreads();                            // (B) scalars ready
        const float c1 = csh[0], c2 = csh[1];

        // ---- Update pass (column tid), fused with yH_{t+1} accumulation ----
        const float p = c1 * s_reg - c2 * yH_reg;   // s_reg = s_t[j], yH_reg = yH_t[j]
        const float q = -c2 * s_reg;
        float yHn = 0.f;
        {
            const float4* s4  = (const float4*)sbuf[cur];
            const float4* hy4 = (const float4*)Hys;
            const float4* yn4 = (const float4*)ybuf[nxt];
            #pragma unroll 8
            for (int i4 = 0; i4 < NN / 4; i4++) {
                float4 ss = s4[i4], hh = hy4[i4], yn = yn4[i4];
                int i = i4 * 4;
                float h0v = H[(i    ) * NPAD + tid] + p * ss.x + q * hh.x;
                float h1v = H[(i + 1) * NPAD + tid] + p * ss.y + q * hh.y;
                float h2v = H[(i + 2) * NPAD + tid] + p * ss.z + q * hh.z;
                float h3v = H[(i + 3) * NPAD + tid] + p * ss.w + q * hh.w;
                H[(i    ) * NPAD + tid] = h0v;
                H[(i + 1) * NPAD + tid] = h1v;
                H[(i + 2) * NPAD + tid] = h2v;
                H[(i + 3) * NPAD + tid] = h3v;
                yHn += yn.x * h0v + yn.y * h1v + yn.z * h2v + yn.w * h3v;
            }
        }
        yH_reg = yHn;            // yH_{t+1}[tid]  (garbage at t==TT-1, unused)
        s_reg = s_n;
        y_reg = y_n;
        __syncthreads();                            // (C) H_t complete
    }

    // ---- Write result (coalesced, conflict-free) ----
    float* op = out + (size_t)pair * NN * NN + tid;
    #pragma unroll 4
    for (int i = 0; i < NN; i++)
        op[i * NN] = H[i * NPAD + tid];
}

extern "C" void kernel_launch(void* const* d_in, const int* in_sizes, int n_in,
                              void* d_out, int out_size)
{
    const float* H0    = (const float*)d_in[0];   // inv_hessian [N,N]
    const float* steps = (const float*)d_in[1];   // [T,B,E,N]
    const float* dgs   = (const float*)d_in[2];   // [T,B,E,N]
    float* out = (float*)d_out;                   // [B,E,N,N]

    cudaFuncSetAttribute(bfgs_kernel,
                         cudaFuncAttributeMaxDynamicSharedMemorySize,
                         (int)SMEM_BYTES);
    bfgs_kernel<<<NPAIRS, NN, SMEM_BYTES>>>(H0, steps, dgs, out);
}

// round 3
// speedup vs baseline: 1.4702x; 1.4702x over previous
#include <cuda_runtime.h>

#define TT 12
#define NNv 192
#define NP 193                     // H0 row pad: conflict-free row & column access
#define KK 24                      // final rank = 2*TT
#define NPAIRS 256
#define TSTRIDE (NPAIRS * NNv)
#define THREADS 384
#define UTP 28                     // transposed-U row pitch (112B rows, 16B-aligned)

// dynamic smem layout (floats)
#define OFF_H0 0
#define OFF_U  (OFF_H0 + NNv * NP)            // 37056
#define OFF_V  (OFF_U + KK * NNv)
#define OFF_G1 (OFF_V + KK * NNv)
#define OFF_G2 (OFF_G1 + TT * NNv)
#define OFF_Y  (OFF_G2 + TT * NNv)
#define OFF_S  (OFF_Y + TT * NNv)
#define SMEM_FLOATS (OFF_S + TT * NNv)        // 55488 floats = 221952 B
#define SMEM_BYTES (SMEM_FLOATS * sizeof(float))

// H_T = H0 + U V^T (rank 24). One CTA per (b,e) pair, 384 threads.
// Phase 1/2: G1[t] = H0 @ y_t, G2[t] = y_t^T @ H0 (batched over all 12 t).
// Phase 3:   serial recurrence builds U,V columns via O(N*t) vector math.
// Phase 4:   out = H0 + U V^T, coalesced writes.
__global__ void __launch_bounds__(THREADS, 1)
bfgs_kernel(const float* __restrict__ H0,
            const float* __restrict__ steps,
            const float* __restrict__ dgs,
            float* __restrict__ out)
{
    extern __shared__ float sm[];
    float* H0s = sm + OFF_H0;
    float* Us  = sm + OFF_U;      // k-major: Us[k*NNv + i]; also GEMV-partial scratch
    float* Vs  = sm + OFF_V;
    float* G1s = sm + OFF_G1;     // [t][i] = (H0 y_t)[i]
    float* G2s = sm + OFF_G2;     // [t][j] = (y_t^T H0)[j]
    float* Ys  = sm + OFF_Y;
    float* Ss  = sm + OFF_S;
    float* UT  = sm + OFF_G1;     // overlay after recurrence: 192*28=5376 <= 9216

    __shared__ float wz[2 * KK];
    __shared__ float Hyv[NNv], yHv[NNv];
    __shared__ float red1[8], red2[8];
    __shared__ float csh[2];

    const int tid  = threadIdx.x;
    const int pair = blockIdx.x;
    const int lane = tid & 31;
    const int wid  = tid >> 5;
    const int half = tid / NNv;          // 0: warps 0-5, 1: warps 6-11
    const int li   = tid - half * NNv;   // 0..191

    const size_t pbase = (size_t)pair * NNv;

    // ---- load H0 (padded), Y, S ----
    for (int idx = tid; idx < NNv * NNv; idx += THREADS)
        H0s[(idx / NNv) * NP + (idx % NNv)] = H0[idx];
    for (int idx = tid; idx < TT * NNv; idx += THREADS) {
        int t = idx / NNv, n = idx - t * NNv;
        Ys[idx] = dgs  [(size_t)t * TSTRIDE + pbase + n];
        Ss[idx] = steps[(size_t)t * TSTRIDE + pbase + n];
    }
    __syncthreads();

    // ---- Phase 1: G1[t][i] = sum_j H0[i][j] * y_t[j]  (thread = row li, j-half) ----
    {
        float acc[TT];
        #pragma unroll
        for (int t = 0; t < TT; t++) acc[t] = 0.f;
        const float* hrow = H0s + li * NP + half * (NNv / 2);
        const int jb0 = half * (NNv / 2);
        #pragma unroll 4
        for (int j4 = 0; j4 < (NNv / 2) / 4; j4++) {
            const int j = j4 * 4;
            const float h0 = hrow[j], h1 = hrow[j + 1], h2 = hrow[j + 2], h3 = hrow[j + 3];
            #pragma unroll
            for (int t = 0; t < TT; t++) {
                float4 yv = *(const float4*)&Ys[t * NNv + jb0 + j];
                acc[t] += h0 * yv.x + h1 * yv.y + h2 * yv.z + h3 * yv.w;
            }
        }
        if (half) {
            #pragma unroll
            for (int t = 0; t < TT; t++) Us[t * NNv + li] = acc[t];
        }
        __syncthreads();
        if (!half) {
            #pragma unroll
            for (int t = 0; t < TT; t++) G1s[t * NNv + li] = acc[t] + Us[t * NNv + li];
        }
        __syncthreads();
    }

    // ---- Phase 2: G2[t][j] = sum_i y_t[i] * H0[i][j]  (thread = col li, i-half) ----
    {
        float acc[TT];
        #pragma unroll
        for (int t = 0; t < TT; t++) acc[t] = 0.f;
        const int ib0 = half * (NNv / 2);
        #pragma unroll 4
        for (int i4 = 0; i4 < (NNv / 2) / 4; i4++) {
            const int i = ib0 + i4 * 4;
            const float h0 = H0s[(i + 0) * NP + li];
            const float h1 = H0s[(i + 1) * NP + li];
            const float h2 = H0s[(i + 2) * NP + li];
            const float h3 = H0s[(i + 3) * NP + li];
            #pragma unroll
            for (int t = 0; t < TT; t++) {
                float4 yv = *(const float4*)&Ys[t * NNv + i];
                acc[t] += h0 * yv.x + h1 * yv.y + h2 * yv.z + h3 * yv.w;
            }
        }
        if (half) {
            #pragma unroll
            for (int t = 0; t < TT; t++) Us[t * NNv + li] = acc[t];
        }
        __syncthreads();
        if (!half) {
            #pragma unroll
            for (int t = 0; t < TT; t++) G2s[t * NNv + li] = acc[t] + Us[t * NNv + li];
        }
        __syncthreads();
    }

    // ---- Phase 3: recurrence, build U,V ----
    for (int t = 0; t < TT; t++) {
        const int k0 = 2 * t;
        // dots: wz[d<k0] = V_d . y_t,  wz[k0+k] = U_k . y_t  (12 warps round-robin)
        const int ndots = 2 * k0;
        for (int d = wid; d < ndots; d += 12) {
            const int k = (d < k0) ? d : (d - k0);
            const float* base = (d < k0) ? (Vs + k * NNv) : (Us + k * NNv);
            float p = 0.f;
            #pragma unroll
            for (int m = 0; m < NNv / 32; m++)
                p += base[lane + 32 * m] * Ys[t * NNv + lane + 32 * m];
            #pragma unroll
            for (int off = 16; off; off >>= 1)
                p += __shfl_down_sync(0xffffffffu, p, off);
            if (lane == 0) wz[d] = p;
        }
        __syncthreads();

        // Hy (threads 0-191) and yH (threads 192-383) in parallel
        if (half == 0) {
            float hy = G1s[t * NNv + li];
            for (int k = 0; k < k0; k++) hy += wz[k] * Us[k * NNv + li];
            Hyv[li] = hy;
        } else {
            float yh = G2s[t * NNv + li];
            for (int k = 0; k < k0; k++) yh += wz[k0 + k] * Vs[k * NNv + li];
            yHv[li] = yh;
        }
        __syncthreads();

        // sdot = s.y, yHy = y.Hy
        if (half == 0) {
            const float sv = Ss[t * NNv + li], yv = Ys[t * NNv + li];
            float v1 = sv * yv;
            float v2 = yv * Hyv[li];
            #pragma unroll
            for (int off = 16; off; off >>= 1) {
                v1 += __shfl_down_sync(0xffffffffu, v1, off);
                v2 += __shfl_down_sync(0xffffffffu, v2, off);
            }
            if (lane == 0) { red1[wid] = v1; red2[wid] = v2; }
        }
        __syncthreads();
        if (tid == 0) {
            float sdot = 0.f, yHy = 0.f;
            #pragma unroll
            for (int w = 0; w < 6; w++) { sdot += red1[w]; yHy += red2[w]; }
            float c1, c2;
            if (sdot != 0.f) { c2 = 1.f / sdot; c1 = (sdot + yHy) * c2 * c2; }
            else             { c1 = 0.f; c2 = 0.f; }
            csh[0] = c1; csh[1] = c2;
        }
        __syncthreads();

        // append 2 columns: dH = s (c1 s - c2 yH)^T + (-c2 Hy) s^T
        if (half == 0) {
            const float c1 = csh[0], c2 = csh[1];
            const float sv = Ss[t * NNv + li];
            Us[(k0    ) * NNv + li] = sv;
            Vs[(k0    ) * NNv + li] = c1 * sv - c2 * yHv[li];
            Us[(k0 + 1) * NNv + li] = -c2 * Hyv[li];
            Vs[(k0 + 1) * NNv + li] = sv;
        }
        __syncthreads();
    }

    // ---- transpose U -> UT[i*28 + k] for float4 broadcast in expansion ----
    for (int idx = tid; idx < KK * NNv; idx += THREADS) {
        const int k = idx / NNv, i2 = idx - k * NNv;
        UT[i2 * UTP + k] = Us[idx];
    }
    __syncthreads();

    // ---- Phase 4: out[i][j] = H0[i][j] + sum_k UT[i][k] * V[k][j] ----
    {
        float vreg[KK];
        #pragma unroll
        for (int k = 0; k < KK; k++) vreg[k] = Vs[k * NNv + li];
        float* op = out + (size_t)pair * NNv * NNv + li;
        const int i0 = half * (NNv / 2);
        #pragma unroll 4
        for (int i = i0; i < i0 + NNv / 2; i++) {
            float r = H0s[i * NP + li];
            const float4* u4 = (const float4*)&UT[i * UTP];
            #pragma unroll
            for (int c = 0; c < KK / 4; c++) {
                float4 uv = u4[c];
                r += uv.x * vreg[4 * c] + uv.y * vreg[4 * c + 1]
                   + uv.z * vreg[4 * c + 2] + uv.w * vreg[4 * c + 3];
            }
            op[(size_t)i * NNv] = r;
        }
    }
}

extern "C" void kernel_launch(void* const* d_in, const int* in_sizes, int n_in,
                              void* d_out, int out_size)
{
    const float* H0    = (const float*)d_in[0];   // [N,N]
    const float* steps = (const float*)d_in[1];   // [T,B,E,N]
    const float* dgs   = (const float*)d_in[2];   // [T,B,E,N]
    float* out = (float*)d_out;                   // [B,E,N,N]

    cudaFuncSetAttribute(bfgs_kernel,
                         cudaFuncAttributeMaxDynamicSharedMemorySize,
                         (int)SMEM_BYTES);
    bfgs_kernel<<<NPAIRS, THREADS, SMEM_BYTES>>>(H0, steps, dgs, out);
}